// round 15
// baseline (speedup 1.0000x reference)
#include <cuda_runtime.h>

#define SEQ  256
#define HID  2048
#define DIM  2048
#define NCTA 128
#define NTHR 1024
#define PJ   704                      // gather columns pinned in smem
#define DYNB (PJ * 64 * 4)            // 180224 bytes dynamic smem

// ---- persistent device state (static allocation: allowed) ----
__device__ float g_Wp[(size_t)NCTA * DIM * 64];   // repacked W_ih: [b][j][64 owned rows]
__device__ __align__(16) float g_h[HID];
__device__ float g_x[DIM];
__device__ volatile unsigned g_c0 = 0;            // barrier channel 0 (x-ready), monotonic
__device__ volatile unsigned g_c1 = 0;            // barrier channel 1 (h-ready), monotonic

// ---- JAX threefry2x32 (exact rounds, partitionable counter layout) ----
__device__ __forceinline__ void tf2x32(unsigned k0, unsigned k1,
                                       unsigned x0, unsigned x1,
                                       unsigned &o0, unsigned &o1) {
  unsigned ks2 = k0 ^ k1 ^ 0x1BD11BDAu;
#define TFR(r) { x0 += x1; x1 = (x1 << (r)) | (x1 >> (32 - (r))); x1 ^= x0; }
  x0 += k0; x1 += k1;
  TFR(13) TFR(15) TFR(26) TFR(6)   x0 += k1;  x1 += ks2 + 1u;
  TFR(17) TFR(29) TFR(16) TFR(24)  x0 += ks2; x1 += k0 + 2u;
  TFR(13) TFR(15) TFR(26) TFR(6)   x0 += k0;  x1 += k1 + 3u;
  TFR(17) TFR(29) TFR(16) TFR(24)  x0 += k1;  x1 += ks2 + 4u;
  TFR(13) TFR(15) TFR(26) TFR(6)   x0 += ks2; x1 += k0 + 5u;
#undef TFR
  o0 = x0; o1 = x1;
}

__device__ __forceinline__ float u01(unsigned bits) {
  return __uint_as_float((bits >> 9) | 0x3f800000u) - 1.0f;
}
__device__ __forceinline__ float sigf(float v) { return 1.0f / (1.0f + expf(-v)); }

extern "C" __global__ void __launch_bounds__(NTHR, 1)
lstm_policy_kernel(const float* __restrict__ A,
                   const float* __restrict__ W_ih,
                   const float* __restrict__ W_hh,
                   const float* __restrict__ b_ih,
                   const float* __restrict__ b_hh,
                   const float* __restrict__ V_w,
                   const float* __restrict__ V_b,
                   const float* __restrict__ temp,
                   float* __restrict__ out)
{
  extern __shared__ float pinW[];     // [PJ][64] pinned gather columns (176KB)

  const int b    = blockIdx.x;
  const int tid  = threadIdx.x;
  const int lane = tid & 31;
  const int w    = tid >> 5;

  __shared__ float h_s[HID];          // 8KB
  __shared__ int   nzi[DIM];          // 8KB
  __shared__ float nzv[DIM];          // 8KB
  __shared__ float4 part4[64][16];    // 16KB gather partials [seg][gate-quad]
  __shared__ float psumV[16][2];
  __shared__ float2 psum2[32];        // A2 partials
  __shared__ float gsum[64];
  __shared__ float c_s[16];
  __shared__ unsigned balx[32];       // compaction ballots
  __shared__ unsigned baly[32];

  // ---- one-time repack: g_Wp[b][j][g] = W_ih[row(g)][j] (pinW aliased as staging) ----
  {
    float (*tile)[65] = (float(*)[65])pinW;   // 64x65 staging
    for (int t = 0; t < 32; ++t) {
      int j0 = t * 64;
      for (int gg = w; gg < 64; gg += 32) {
        int row = (gg >> 4) * HID + b * 16 + (gg & 15);
        for (int jj = lane; jj < 64; jj += 32)
          tile[jj][gg] = W_ih[(size_t)row * DIM + j0 + jj];
      }
      __syncthreads();
      for (int jj = w; jj < 64; jj += 32) {
        float* dst = &g_Wp[((size_t)b * DIM + j0 + jj) * 64];
        for (int gg = lane; gg < 64; gg += 32) dst[gg] = tile[jj][gg];
      }
      __syncthreads();
    }
    // fill pinned gather region from own repacked slice (contiguous copy)
    const float* src = &g_Wp[(size_t)b * DIM * 64];
    for (int i = tid; i < PJ * 64; i += NTHR) pinW[i] = src[i];
  }
  if (tid < 16) c_s[tid] = 0.0f;
  __syncthreads();

  const float temperature = __ldg(temp);
  const float4* H4 = (const float4*)h_s;

  for (int step = 0; step < SEQ; ++step) {
    unsigned sk0, sk1;
    tf2x32(0u, 42u, 0u, (unsigned)step, sk0, sk1);

    // load h into smem
    for (int i = tid; i < HID; i += NTHR)
      h_s[i] = (step == 0) ? 0.0f : __ldcg(&g_h[i]);
    __syncthreads();                                   // (1)

    // ====== Phase A1: V_w rows as half-dots (fast x publication) ======
    {
      int r16 = w >> 1, hf = w & 1;
      const float4* R  = (const float4*)(V_w + (size_t)(b * 16 + r16) * DIM) + hf * 256;
      const float4* Hh = H4 + hf * 256;
      float s = 0.0f;
      #pragma unroll
      for (int k = 0; k < 8; ++k) {
        float4 a  = __ldg(R + k * 32 + lane);
        float4 hh = Hh[k * 32 + lane];
        s += a.x * hh.x + a.y * hh.y + a.z * hh.z + a.w * hh.w;
      }
      #pragma unroll
      for (int o = 16; o > 0; o >>= 1) s += __shfl_xor_sync(0xffffffffu, s, o);
      if (lane == 0) psumV[r16][hf] = s;
    }
    __syncthreads();                                   // (2)
    if (tid < 16) {
      float sv = psumV[tid][0] + psumV[tid][1];
      int r = b * 16 + tid;
      float z  = temperature * (sv + __ldg(&V_b[r]));
      float pi = sigf(z);
      unsigned y0, y1;
      tf2x32(sk0, sk1, 0u, (unsigned)r, y0, y1);
      float u   = u01(y0 ^ y1);
      float act = (u < pi) ? 1.0f : 0.0f;
      __stcs(&out[(size_t)step * DIM + r], act);
      __stcs(&out[(size_t)SEQ * DIM + (size_t)step * DIM + r], pi);
      __stcg(&g_x[r], act * __ldg(&A[r]));
    }
    __syncthreads();                                   // (3) x writes visible
    if (tid == 0) {                                    // barrier-1 ARRIVE (hidden)
      __threadfence();
      atomicAdd((unsigned*)&g_c0, 1u);
    }

    // ====== Phase A2: W_hh — gates (w, 32+w) per warp, 2 accumulators ======
    {
      int rowA = (w >> 4) * HID + b * 16 + (w & 15);
      int lg = 32 + w;
      int rowB = (lg >> 4) * HID + b * 16 + (lg & 15);
      const float4* RA = (const float4*)(W_hh + (size_t)rowA * DIM);
      const float4* RB = (const float4*)(W_hh + (size_t)rowB * DIM);
      float sA = 0.0f, sB = 0.0f;
      #pragma unroll
      for (int k = 0; k < 16; ++k) {
        float4 a  = __ldg(RA + k * 32 + lane);
        float4 bb = __ldg(RB + k * 32 + lane);
        float4 hh = H4[k * 32 + lane];
        sA += a.x  * hh.x + a.y  * hh.y + a.z  * hh.z + a.w  * hh.w;
        sB += bb.x * hh.x + bb.y * hh.y + bb.z * hh.z + bb.w * hh.w;
      }
      #pragma unroll
      for (int o = 16; o > 0; o >>= 1) {
        sA += __shfl_xor_sync(0xffffffffu, sA, o);
        sB += __shfl_xor_sync(0xffffffffu, sB, o);
      }
      if (lane == 0) psum2[w] = make_float2(sA, sB);
    }
    // (no sync here — psum2 is consumed only after sync (4))

    // barrier-1 WAIT: all CTAs' x written
    if (tid == 0) {
      unsigned tgt = (unsigned)NCTA * (unsigned)(step + 1);
      while (g_c0 < tgt) { }
      __threadfence();                                 // acquire
    }
    __syncthreads();                                   // (4) covers psum2 + x-ready

    // ====== Phase B: compact nonzeros of x (2 syncs), gather ======
    int len, len0, myoff;
    unsigned b0, b1;
    float v0, v1;
    {
      int base = w * 64;
      v0 = __ldcg(&g_x[base + lane]);
      v1 = __ldcg(&g_x[base + 32 + lane]);
      b0 = __ballot_sync(0xffffffffu, v0 != 0.0f);
      b1 = __ballot_sync(0xffffffffu, v1 != 0.0f);
      if (lane == 0) { balx[w] = b0; baly[w] = b1; }
    }
    __syncthreads();                                   // (5) ballots ready
    {
      // per-thread redundant prefix over 32 warp-ballots
      int off = 0; len = 0; len0 = 0;
      #pragma unroll
      for (int w2 = 0; w2 < 32; ++w2) {
        int c = __popc(balx[w2]) + __popc(baly[w2]);
        if (w2 < w)       off  += c;
        if (w2 < PJ / 64) len0 += c;
        len += c;
      }
      myoff = off;
      int base = w * 64;
      unsigned mlo = (1u << lane) - 1u;
      if (v0 != 0.0f) { int p = myoff + __popc(b0 & mlo); nzi[p] = base + lane; nzv[p] = v0; }
      if (v1 != 0.0f) { int p = myoff + __popc(b0) + __popc(b1 & mlo); nzi[p] = base + 32 + lane; nzv[p] = v1; }
    }
    __syncthreads();                                   // (6) nz list ready

    {
      const int seg = tid >> 4;           // 64 segments
      const int g4  = tid & 15;           // gate quad (4 gates per thread)
      const float4* wp4  = (const float4*)g_Wp + (size_t)b * (DIM * 16) + g4;
      const float4* pin4 = (const float4*)pinW + g4;
      int kb0 = (len * seg) >> 6;
      int kb1 = (len * (seg + 1)) >> 6;
      int ks = kb1 < len0 ? kb1 : len0;   // end of pinned part
      int kg = kb0 > len0 ? kb0 : len0;   // start of global part
      float4 accG = make_float4(0.f, 0.f, 0.f, 0.f);
      float4 accP = make_float4(0.f, 0.f, 0.f, 0.f);
      // global streaming part FIRST (long-latency loads drain while smem part runs)
      #pragma unroll 8
      for (int k = kg; k < kb1; ++k) {
        float4 wv = __ldcs(wp4 + (size_t)nzi[k] * 16);
        float xv = nzv[k];
        accG.x = fmaf(xv, wv.x, accG.x);
        accG.y = fmaf(xv, wv.y, accG.y);
        accG.z = fmaf(xv, wv.z, accG.z);
        accG.w = fmaf(xv, wv.w, accG.w);
      }
      #pragma unroll 4
      for (int k = kb0; k < ks; ++k) {
        float4 wv = pin4[(size_t)nzi[k] * 16];
        float xv = nzv[k];
        accP.x = fmaf(xv, wv.x, accP.x);
        accP.y = fmaf(xv, wv.y, accP.y);
        accP.z = fmaf(xv, wv.z, accP.z);
        accP.w = fmaf(xv, wv.w, accP.w);
      }
      part4[seg][g4] = make_float4(accP.x + accG.x, accP.y + accG.y,
                                   accP.z + accG.z, accP.w + accG.w);
    }
    __syncthreads();                                   // (7) part4 ready

    // ====== Final combine: A2 partials + biases + gather partials ======
    if (tid < 64) {
      // gates 0..31 -> psum2[g].x ; 32..63 -> psum2[g-32].y
      float sv = (tid < 32) ? psum2[tid].x : psum2[tid - 32].y;
      int row = (tid >> 4) * HID + b * 16 + (tid & 15);
      float s2 = sv + __ldg(&b_ih[row]) + __ldg(&b_hh[row]);
      const int gp = tid >> 2, comp = tid & 3;
      const float* pp = (const float*)&part4[0][gp] + comp;
      #pragma unroll
      for (int s3 = 0; s3 < 64; ++s3) s2 += pp[(size_t)s3 * 64];
      gsum[tid] = s2;
    }
    __syncthreads();                                   // (8)

    if (tid < 16) {
      float ig = gsum[tid];
      float fg = gsum[16 + tid];
      float gg = gsum[32 + tid];
      float og = gsum[48 + tid];
      float cn = sigf(fg) * c_s[tid] + sigf(ig) * tanhf(gg);
      float hn = sigf(og) * tanhf(cn);
      c_s[tid] = cn;
      __stcg(&g_h[b * 16 + tid], hn);
    }
    __syncthreads();                                   // (9) h writes visible
    if (tid == 0) {                                    // barrier-2 arrive + wait
      __threadfence();
      atomicAdd((unsigned*)&g_c1, 1u);
      unsigned tgt = (unsigned)NCTA * (unsigned)(step + 1);
      while (g_c1 < tgt) { }
      __threadfence();                                 // acquire
    }
    __syncthreads();                                   // (10)
  }

  // ---- exit barrier + counter reset (keeps graph replays correct) ----
  __syncthreads();
  if (tid == 0) {
    atomicAdd((unsigned*)&g_c0, 1u);
    if (b == 0) {
      unsigned tgt = (unsigned)NCTA * (unsigned)SEQ + (unsigned)NCTA;
      while (g_c0 < tgt) { }
      g_c0 = 0u;
      g_c1 = 0u;
      __threadfence();
    }
  }
}

extern "C" void kernel_launch(void* const* d_in, const int* in_sizes, int n_in,
                              void* d_out, int out_size) {
  (void)in_sizes; (void)n_in; (void)out_size;
  cudaFuncSetAttribute(lstm_policy_kernel,
                       cudaFuncAttributeMaxDynamicSharedMemorySize, DYNB);
  lstm_policy_kernel<<<NCTA, NTHR, DYNB>>>(
      (const float*)d_in[0],  // A
      (const float*)d_in[1],  // W_ih
      (const float*)d_in[2],  // W_hh
      (const float*)d_in[3],  // b_ih
      (const float*)d_in[4],  // b_hh
      (const float*)d_in[5],  // V_w
      (const float*)d_in[6],  // V_b
      (const float*)d_in[7],  // temperature
      (float*)d_out);
}

// round 16
// speedup vs baseline: 1.1439x; 1.1439x over previous
#include <cuda_runtime.h>

#define SEQ  256
#define HID  2048
#define DIM  2048
#define NCTA 128
#define NTHR 1024
#define PJ   704                      // gather columns pinned in smem
#define DYNB (PJ * 64 * 4)            // 180224 bytes dynamic smem

// ---- persistent device state (static allocation: allowed) ----
__device__ float g_Wp[(size_t)NCTA * DIM * 64];   // repacked W_ih: [b][j][64 owned rows]
__device__ __align__(16) float g_h[HID];
__device__ float g_x[DIM];
__device__ volatile unsigned g_c0 = 0;            // barrier channel 0 (x-ready), monotonic
__device__ volatile unsigned g_c1 = 0;            // barrier channel 1 (h-ready), monotonic

// ---- JAX threefry2x32 (exact rounds, partitionable counter layout) ----
__device__ __forceinline__ void tf2x32(unsigned k0, unsigned k1,
                                       unsigned x0, unsigned x1,
                                       unsigned &o0, unsigned &o1) {
  unsigned ks2 = k0 ^ k1 ^ 0x1BD11BDAu;
#define TFR(r) { x0 += x1; x1 = (x1 << (r)) | (x1 >> (32 - (r))); x1 ^= x0; }
  x0 += k0; x1 += k1;
  TFR(13) TFR(15) TFR(26) TFR(6)   x0 += k1;  x1 += ks2 + 1u;
  TFR(17) TFR(29) TFR(16) TFR(24)  x0 += ks2; x1 += k0 + 2u;
  TFR(13) TFR(15) TFR(26) TFR(6)   x0 += k0;  x1 += k1 + 3u;
  TFR(17) TFR(29) TFR(16) TFR(24)  x0 += k1;  x1 += ks2 + 4u;
  TFR(13) TFR(15) TFR(26) TFR(6)   x0 += ks2; x1 += k0 + 5u;
#undef TFR
  o0 = x0; o1 = x1;
}

__device__ __forceinline__ float u01(unsigned bits) {
  return __uint_as_float((bits >> 9) | 0x3f800000u) - 1.0f;
}
__device__ __forceinline__ float sigf(float v) { return 1.0f / (1.0f + expf(-v)); }

extern "C" __global__ void __launch_bounds__(NTHR, 1)
lstm_policy_kernel(const float* __restrict__ A,
                   const float* __restrict__ W_ih,
                   const float* __restrict__ W_hh,
                   const float* __restrict__ b_ih,
                   const float* __restrict__ b_hh,
                   const float* __restrict__ V_w,
                   const float* __restrict__ V_b,
                   const float* __restrict__ temp,
                   float* __restrict__ out)
{
  extern __shared__ float pinW[];     // [PJ][64] pinned gather columns (176KB)

  const int b    = blockIdx.x;
  const int tid  = threadIdx.x;
  const int lane = tid & 31;
  const int w    = tid >> 5;

  __shared__ float h_s[HID];          // 8KB
  __shared__ int   nzi[DIM];          // 8KB
  __shared__ float nzv[DIM];          // 8KB
  __shared__ float4 part4[64][16];    // 16KB gather partials [seg][gate-quad]
  __shared__ float psumV[16][2];
  __shared__ float2 psum2[32];
  __shared__ float gsum[64];
  __shared__ float c_s[16];
  __shared__ int   wcnt[32];
  __shared__ int   woff[33];

  // ---- one-time repack: g_Wp[b][j][g] = W_ih[row(g)][j] (pinW aliased as staging) ----
  {
    float (*tile)[65] = (float(*)[65])pinW;   // 64x65 staging
    for (int t = 0; t < 32; ++t) {
      int j0 = t * 64;
      for (int gg = w; gg < 64; gg += 32) {
        int row = (gg >> 4) * HID + b * 16 + (gg & 15);
        for (int jj = lane; jj < 64; jj += 32)
          tile[jj][gg] = W_ih[(size_t)row * DIM + j0 + jj];
      }
      __syncthreads();
      for (int jj = w; jj < 64; jj += 32) {
        float* dst = &g_Wp[((size_t)b * DIM + j0 + jj) * 64];
        for (int gg = lane; gg < 64; gg += 32) dst[gg] = tile[jj][gg];
      }
      __syncthreads();
    }
    // fill pinned gather region from own repacked slice (contiguous copy)
    const float* src = &g_Wp[(size_t)b * DIM * 64];
    for (int i = tid; i < PJ * 64; i += NTHR) pinW[i] = src[i];
  }
  if (tid < 16) c_s[tid] = 0.0f;
  __syncthreads();

  const float temperature = __ldg(temp);
  const float4* H4 = (const float4*)h_s;

  for (int step = 0; step < SEQ; ++step) {
    unsigned sk0, sk1;
    tf2x32(0u, 42u, 0u, (unsigned)step, sk0, sk1);

    // load h into smem
    for (int i = tid; i < HID; i += NTHR)
      h_s[i] = (step == 0) ? 0.0f : __ldcg(&g_h[i]);
    __syncthreads();

    // ====== Phase A1: V_w rows as half-dots (fast x publication) ======
    {
      int r16 = w >> 1, hf = w & 1;
      const float4* R  = (const float4*)(V_w + (size_t)(b * 16 + r16) * DIM) + hf * 256;
      const float4* Hh = H4 + hf * 256;
      float s = 0.0f;
      #pragma unroll
      for (int k = 0; k < 8; ++k) {
        float4 a  = __ldg(R + k * 32 + lane);
        float4 hh = Hh[k * 32 + lane];
        s += a.x * hh.x + a.y * hh.y + a.z * hh.z + a.w * hh.w;
      }
      #pragma unroll
      for (int o = 16; o > 0; o >>= 1) s += __shfl_xor_sync(0xffffffffu, s, o);
      if (lane == 0) psumV[r16][hf] = s;
    }
    __syncthreads();
    if (tid < 16) {
      float sv = psumV[tid][0] + psumV[tid][1];
      int r = b * 16 + tid;
      float z  = temperature * (sv + __ldg(&V_b[r]));
      float pi = sigf(z);
      unsigned y0, y1;
      tf2x32(sk0, sk1, 0u, (unsigned)r, y0, y1);
      float u   = u01(y0 ^ y1);
      float act = (u < pi) ? 1.0f : 0.0f;
      __stcs(&out[(size_t)step * DIM + r], act);
      __stcs(&out[(size_t)SEQ * DIM + (size_t)step * DIM + r], pi);
      __stcg(&g_x[r], act * __ldg(&A[r]));
    }
    __syncthreads();                                   // x writes visible to block
    if (tid == 0) {                                    // barrier-1 ARRIVE (hidden):
      __threadfence();                                 // single-thread cumulative fence
      atomicAdd((unsigned*)&g_c0, 1u);
    }

    // ====== Phase A2: W_hh — gates (w, 32+w) per warp, 2 accumulators ======
    {
      int rowA = (w >> 4) * HID + b * 16 + (w & 15);
      int lg = 32 + w;
      int rowB = (lg >> 4) * HID + b * 16 + (lg & 15);
      const float4* RA = (const float4*)(W_hh + (size_t)rowA * DIM);
      const float4* RB = (const float4*)(W_hh + (size_t)rowB * DIM);
      float sA = 0.0f, sB = 0.0f;
      #pragma unroll
      for (int k = 0; k < 16; ++k) {
        float4 a  = __ldg(RA + k * 32 + lane);
        float4 bb = __ldg(RB + k * 32 + lane);
        float4 hh = H4[k * 32 + lane];
        sA += a.x  * hh.x + a.y  * hh.y + a.z  * hh.z + a.w  * hh.w;
        sB += bb.x * hh.x + bb.y * hh.y + bb.z * hh.z + bb.w * hh.w;
      }
      #pragma unroll
      for (int o = 16; o > 0; o >>= 1) {
        sA += __shfl_xor_sync(0xffffffffu, sA, o);
        sB += __shfl_xor_sync(0xffffffffu, sB, o);
      }
      if (lane == 0) psum2[w] = make_float2(sA, sB);
    }
    __syncthreads();
    if (tid < 64) {
      float sv = (tid < 32) ? psum2[tid].x : psum2[tid - 32].y;
      int row = (tid >> 4) * HID + b * 16 + (tid & 15);
      gsum[tid] = sv + __ldg(&b_ih[row]) + __ldg(&b_hh[row]);
    }

    // barrier-1 WAIT: all CTAs' x written
    if (tid == 0) {
      unsigned tgt = (unsigned)NCTA * (unsigned)(step + 1);
      while (g_c0 < tgt) { }
      __threadfence();                                 // acquire
    }
    __syncthreads();

    // ====== Phase B: compact nonzeros of x, split smem/global float4 gather ======
    {
      int base = w * 64;
      float v0 = __ldcg(&g_x[base + lane]);
      float v1 = __ldcg(&g_x[base + 32 + lane]);
      unsigned b0 = __ballot_sync(0xffffffffu, v0 != 0.0f);
      unsigned b1 = __ballot_sync(0xffffffffu, v1 != 0.0f);
      if (lane == 0) wcnt[w] = __popc(b0) + __popc(b1);
      __syncthreads();
      if (w == 0) {
        int c2 = wcnt[lane];
        int xs = c2;
        #pragma unroll
        for (int o = 1; o < 32; o <<= 1) {
          int y = __shfl_up_sync(0xffffffffu, xs, o);
          if (lane >= o) xs += y;
        }
        woff[lane] = xs - c2;
        if (lane == 31) woff[32] = xs;
      }
      __syncthreads();
      int off = woff[w];
      unsigned mlo = (1u << lane) - 1u;
      if (v0 != 0.0f) { int p = off + __popc(b0 & mlo); nzi[p] = base + lane; nzv[p] = v0; }
      if (v1 != 0.0f) { int p = off + __popc(b0) + __popc(b1 & mlo); nzi[p] = base + 32 + lane; nzv[p] = v1; }
      __syncthreads();
    }
    const int len  = woff[32];
    const int len0 = woff[PJ / 64];   // nonzeros with j < PJ (smem-pinned prefix)

    {
      const int seg = tid >> 4;           // 64 segments
      const int g4  = tid & 15;           // gate quad (4 gates per thread)
      const float4* wp4  = (const float4*)g_Wp + (size_t)b * (DIM * 16) + g4;
      const float4* pin4 = (const float4*)pinW + g4;
      int kb0 = (len * seg) >> 6;
      int kb1 = (len * (seg + 1)) >> 6;
      float4 acc = make_float4(0.f, 0.f, 0.f, 0.f);
      int ks = kb1 < len0 ? kb1 : len0;
      #pragma unroll 4
      for (int k = kb0; k < ks; ++k) {                 // smem-pinned part
        float4 wv = pin4[(size_t)nzi[k] * 16];
        float xv = nzv[k];
        acc.x = fmaf(xv, wv.x, acc.x);
        acc.y = fmaf(xv, wv.y, acc.y);
        acc.z = fmaf(xv, wv.z, acc.z);
        acc.w = fmaf(xv, wv.w, acc.w);
      }
      int kg = kb0 > len0 ? kb0 : len0;
      #pragma unroll 8
      for (int k = kg; k < kb1; ++k) {                 // global streaming part
        float4 wv = __ldcs(wp4 + (size_t)nzi[k] * 16);
        float xv = nzv[k];
        acc.x = fmaf(xv, wv.x, acc.x);
        acc.y = fmaf(xv, wv.y, acc.y);
        acc.z = fmaf(xv, wv.z, acc.z);
        acc.w = fmaf(xv, wv.w, acc.w);
      }
      part4[seg][g4] = acc;
    }
    __syncthreads();
    if (tid < 64) {
      float s2 = gsum[tid];
      const int gp = tid >> 2, comp = tid & 3;
      const float* pp = (const float*)&part4[0][gp] + comp;
      #pragma unroll
      for (int s3 = 0; s3 < 64; ++s3) s2 += pp[(size_t)s3 * 64];
      gsum[tid] = s2;
    }
    __syncthreads();

    if (tid < 16) {
      float ig = gsum[tid];
      float fg = gsum[16 + tid];
      float gg = gsum[32 + tid];
      float og = gsum[48 + tid];
      float cn = sigf(fg) * c_s[tid] + sigf(ig) * tanhf(gg);
      float hn = sigf(og) * tanhf(cn);
      c_s[tid] = cn;
      __stcg(&g_h[b * 16 + tid], hn);
    }
    __syncthreads();                                   // h writes visible to block
    if (tid == 0) {                                    // barrier-2 arrive + wait
      __threadfence();                                 // single-thread cumulative fence
      atomicAdd((unsigned*)&g_c1, 1u);
      unsigned tgt = (unsigned)NCTA * (unsigned)(step + 1);
      while (g_c1 < tgt) { }
      __threadfence();                                 // acquire
    }
    __syncthreads();
  }

  // ---- exit barrier + counter reset (keeps graph replays correct) ----
  __syncthreads();
  if (tid == 0) {
    atomicAdd((unsigned*)&g_c0, 1u);
    if (b == 0) {
      unsigned tgt = (unsigned)NCTA * (unsigned)SEQ + (unsigned)NCTA;
      while (g_c0 < tgt) { }
      g_c0 = 0u;
      g_c1 = 0u;
      __threadfence();
    }
  }
}

extern "C" void kernel_launch(void* const* d_in, const int* in_sizes, int n_in,
                              void* d_out, int out_size) {
  (void)in_sizes; (void)n_in; (void)out_size;
  cudaFuncSetAttribute(lstm_policy_kernel,
                       cudaFuncAttributeMaxDynamicSharedMemorySize, DYNB);
  lstm_policy_kernel<<<NCTA, NTHR, DYNB>>>(
      (const float*)d_in[0],  // A
      (const float*)d_in[1],  // W_ih
      (const float*)d_in[2],  // W_hh
      (const float*)d_in[3],  // b_ih
      (const float*)d_in[4],  // b_hh
      (const float*)d_in[5],  // V_w
      (const float*)d_in[6],  // V_b
      (const float*)d_in[7],  // temperature
      (float*)d_out);
}